// round 1
// baseline (speedup 1.0000x reference)
#include <cuda_runtime.h>
#include <math.h>

// Problem constants
#define B_ 2
#define H_ 16
#define S_ 2048
#define D_ 64

// Tiling
#define BQ 16          // query rows per CTA
#define KT 256         // K/V rows staged in smem per tile
#define VT 64          // k-rows per PV group per tile (KT / 4 groups)
#define NTHREADS 256

// Shared-memory row strides (floats). KROW = 68 (17 float4s, odd -> conflict-free
// LDS.128 for lane-consecutive rows). SROW = 2052 (float4-aligned, breaks 2^n aliasing).
#define KROW 68
#define SROW 2052

#define Q_S_OFF 0
#define KT_OFF  (BQ * KROW)                 // 1088
#define S_OFF   (KT_OFF + KT * KROW)        // 18496
#define RS_OFF  (S_OFF + BQ * SROW)         // 51328
#define SMEM_FLOATS (RS_OFF + BQ)           // 51344 floats = 205,376 B
#define SMEM_BYTES (SMEM_FLOATS * 4)

__global__ __launch_bounds__(NTHREADS, 1)
void attn_alibi_kernel(const float* __restrict__ Q, const float* __restrict__ K,
                       const float* __restrict__ V, const int* __restrict__ Msk,
                       const float* __restrict__ Alb, float* __restrict__ Out,
                       float* __restrict__ P) {
    extern __shared__ float sm[];
    float* q_s  = sm + Q_S_OFF;   // [BQ][KROW]
    float* kt   = sm + KT_OFF;    // [KT][KROW]  (K tiles, then V tiles, then PV reduce)
    float* s    = sm + S_OFF;     // [BQ][SROW]  score strip
    float* rinv = sm + RS_OFF;    // [BQ] 1/rowsum

    const int h  = blockIdx.x;
    const int qb = blockIdx.y;
    const int b  = blockIdx.z;
    const int t  = threadIdx.x;

    const size_t bh = (size_t)b * H_ + h;
    const float* Qp = Q + (bh * S_ + (size_t)qb * BQ) * D_;
    const float* Kp = K + bh * S_ * D_;
    const float* Vp = V + bh * S_ * D_;

    // ---- load Q tile: 16 rows x 64 floats = 256 float4, one per thread ----
    {
        int row = t >> 4, d4 = t & 15;
        float4 v = reinterpret_cast<const float4*>(Qp)[row * 16 + d4];
        *reinterpret_cast<float4*>(&q_s[row * KROW + d4 * 4]) = v;
    }

    // ================= Phase 1: raw scores QK^T into smem =================
    const int qg = t >> 6;   // 0..3 : q-row group (4 rows)
    const int kg = t & 63;   // 0..63: k base; this thread's k cols = kg + 64*j

    for (int k0 = 0; k0 < S_; k0 += KT) {
        __syncthreads();   // q_s ready (iter 0) / previous tile consumed
        const float4* Ksrc = reinterpret_cast<const float4*>(Kp + (size_t)k0 * D_);
        #pragma unroll
        for (int it = 0; it < 16; ++it) {
            int idx = t + it * NTHREADS;       // 0..4095
            int row = idx >> 4, d4 = idx & 15;
            *reinterpret_cast<float4*>(&kt[row * KROW + d4 * 4]) = Ksrc[idx];
        }
        __syncthreads();

        float acc[4][4];
        #pragma unroll
        for (int i = 0; i < 4; ++i)
            #pragma unroll
            for (int j = 0; j < 4; ++j) acc[i][j] = 0.0f;

        #pragma unroll 4
        for (int d4 = 0; d4 < 16; ++d4) {
            float4 qv[4], kv[4];
            #pragma unroll
            for (int i = 0; i < 4; ++i)
                qv[i] = *reinterpret_cast<const float4*>(&q_s[(qg * 4 + i) * KROW + d4 * 4]);
            #pragma unroll
            for (int j = 0; j < 4; ++j)
                kv[j] = *reinterpret_cast<const float4*>(&kt[(kg + 64 * j) * KROW + d4 * 4]);
            #pragma unroll
            for (int i = 0; i < 4; ++i)
                #pragma unroll
                for (int j = 0; j < 4; ++j)
                    acc[i][j] += qv[i].x * kv[j].x + qv[i].y * kv[j].y +
                                 qv[i].z * kv[j].z + qv[i].w * kv[j].w;
        }
        #pragma unroll
        for (int i = 0; i < 4; ++i)
            #pragma unroll
            for (int j = 0; j < 4; ++j)
                s[(qg * 4 + i) * SROW + k0 + kg + 64 * j] = acc[i][j];
    }
    __syncthreads();

    // ========= Phase 2: scale + alibi + mask + softmax (exact) =========
    {
        const int w    = t >> 5;   // warp 0..7 -> rows 2w, 2w+1
        const int lane = t & 31;
        const float slope = exp2f(-8.0f * (float)(h + 1) / (float)H_);  // (2^-8/H)^(h+1)
        const float* al = Alb + ((size_t)b * S_ + (size_t)qb * BQ) * S_;
        const int*   mk = Msk + ((size_t)b * S_ + (size_t)qb * BQ) * S_;

        #pragma unroll
        for (int rr = 0; rr < 2; ++rr) {
            const int r = w * 2 + rr;
            float*       srow = s  + (size_t)r * SROW;
            const float* arow = al + (size_t)r * S_;
            const int*   mrow = mk + (size_t)r * S_;

            float m = -3.0e38f;
            for (int k = lane; k < S_; k += 32) {
                float v = srow[k] * 0.125f + arow[k] * slope;
                if (mrow[k] == 0) v = -1.0e9f;
                srow[k] = v;
                m = fmaxf(m, v);
            }
            #pragma unroll
            for (int off = 16; off > 0; off >>= 1)
                m = fmaxf(m, __shfl_xor_sync(0xffffffffu, m, off));

            float sum = 0.0f;
            for (int k = lane; k < S_; k += 32) {
                float e = __expf(srow[k] - m);
                srow[k] = e;          // keep UNNORMALIZED e; normalize at output
                sum += e;
            }
            #pragma unroll
            for (int off = 16; off > 0; off >>= 1)
                sum += __shfl_xor_sync(0xffffffffu, sum, off);
            const float inv = 1.0f / sum;
            if (lane == 0) rinv[r] = inv;

            if (P) {   // write normalized p_attn, coalesced
                float* prow = P + ((bh * S_ + (size_t)qb * BQ + r)) * S_;
                for (int k = lane; k < S_; k += 32)
                    prow[k] = srow[k] * inv;
            }
        }
    }
    __syncthreads();

    // ================= Phase 3: Out = P @ V (4-way k-split) =================
    {
        const int g  = t >> 6;          // k-split group 0..3
        const int tt = t & 63;
        const int r0 = (tt >> 4) * 4;   // 4 q-rows
        const int c4 = (tt & 15) * 4;   // 4 d-cols

        float oacc[4][4];
        #pragma unroll
        for (int i = 0; i < 4; ++i)
            #pragma unroll
            for (int j = 0; j < 4; ++j) oacc[i][j] = 0.0f;

        for (int kb = 0; kb < S_; kb += KT) {
            __syncthreads();
            const float4* Vsrc = reinterpret_cast<const float4*>(Vp + (size_t)kb * D_);
            #pragma unroll
            for (int it = 0; it < 16; ++it) {
                int idx = t + it * NTHREADS;
                int row = idx >> 4, d4 = idx & 15;
                *reinterpret_cast<float4*>(&kt[row * KROW + d4 * 4]) = Vsrc[idx];
            }
            __syncthreads();

            const int kl0 = g * VT;     // this group's rows within the staged tile
            #pragma unroll 4
            for (int kk = 0; kk < VT; kk += 4) {
                float4 v0 = *reinterpret_cast<const float4*>(&kt[(kl0 + kk + 0) * KROW + c4]);
                float4 v1 = *reinterpret_cast<const float4*>(&kt[(kl0 + kk + 1) * KROW + c4]);
                float4 v2 = *reinterpret_cast<const float4*>(&kt[(kl0 + kk + 2) * KROW + c4]);
                float4 v3 = *reinterpret_cast<const float4*>(&kt[(kl0 + kk + 3) * KROW + c4]);
                #pragma unroll
                for (int i = 0; i < 4; ++i) {
                    float4 p = *reinterpret_cast<const float4*>(&s[(r0 + i) * SROW + kb + kl0 + kk]);
                    oacc[i][0] += p.x * v0.x + p.y * v1.x + p.z * v2.x + p.w * v3.x;
                    oacc[i][1] += p.x * v0.y + p.y * v1.y + p.z * v2.y + p.w * v3.y;
                    oacc[i][2] += p.x * v0.z + p.y * v1.z + p.z * v2.z + p.w * v3.z;
                    oacc[i][3] += p.x * v0.w + p.y * v1.w + p.z * v2.w + p.w * v3.w;
                }
            }
        }

        // cross-group reduction through smem (kt is free now)
        __syncthreads();
        #pragma unroll
        for (int i = 0; i < 4; ++i)
            *reinterpret_cast<float4*>(&kt[g * (BQ * D_) + (r0 + i) * D_ + c4]) =
                make_float4(oacc[i][0], oacc[i][1], oacc[i][2], oacc[i][3]);
        __syncthreads();

        {
            int row = t >> 4, co = (t & 15) * 4;
            float4 a0 = *reinterpret_cast<const float4*>(&kt[0 * (BQ * D_) + row * D_ + co]);
            float4 a1 = *reinterpret_cast<const float4*>(&kt[1 * (BQ * D_) + row * D_ + co]);
            float4 a2 = *reinterpret_cast<const float4*>(&kt[2 * (BQ * D_) + row * D_ + co]);
            float4 a3 = *reinterpret_cast<const float4*>(&kt[3 * (BQ * D_) + row * D_ + co]);
            const float invs = rinv[row];
            float4 r;
            r.x = (a0.x + a1.x + a2.x + a3.x) * invs;
            r.y = (a0.y + a1.y + a2.y + a3.y) * invs;
            r.z = (a0.z + a1.z + a2.z + a3.z) * invs;
            r.w = (a0.w + a1.w + a2.w + a3.w) * invs;
            float* orow = Out + (bh * S_ + (size_t)qb * BQ + row) * D_;
            *reinterpret_cast<float4*>(&orow[co]) = r;
        }
    }
}

extern "C" void kernel_launch(void* const* d_in, const int* in_sizes, int n_in,
                              void* d_out, int out_size) {
    const float* Q  = (const float*)d_in[0];
    const float* K  = (const float*)d_in[1];
    const float* V  = (const float*)d_in[2];
    const int*   M  = (const int*)d_in[3];
    const float* A  = (const float*)d_in[4];
    float* Out = (float*)d_out;

    const long long OUT_E = (long long)B_ * H_ * S_ * D_;          // 4,194,304
    const long long P_E   = (long long)B_ * H_ * S_ * (long long)S_; // 134,217,728
    float* P = ((long long)out_size >= OUT_E + P_E) ? (Out + OUT_E) : nullptr;

    cudaFuncSetAttribute(attn_alibi_kernel,
                         cudaFuncAttributeMaxDynamicSharedMemorySize, SMEM_BYTES);

    dim3 grid(H_, S_ / BQ, B_);   // h fastest -> heads of same (b,q-block) adjacent for L2 reuse
    attn_alibi_kernel<<<grid, NTHREADS, SMEM_BYTES>>>(Q, K, V, M, A, Out, P);
}

// round 4
// speedup vs baseline: 1.3598x; 1.3598x over previous
#include <cuda_runtime.h>
#include <cuda_bf16.h>
#include <stdint.h>
#include <math.h>

// Problem constants
#define B_ 2
#define H_ 16
#define S_ 2048
#define D_ 64

// Tiling
#define BQ 16          // query rows per CTA
#define KT 256         // K/V rows staged in smem per tile
#define NTHREADS 256   // 8 warps

#define KROWB 72       // bf16 elems per staged K/V row (64 + 8 pad -> conflict-free frags)
#define SROW  2056     // fp32 score-strip row stride
#define REDROW 68      // fp32 reduce-area row stride

// Shared memory byte offsets
#define S_OFFB     0
#define RINV_OFFB  (BQ * SROW * 4)                 // 131584
#define QHI_OFFB   (RINV_OFFB + 64)                // 131648
#define QLO_OFFB   (QHI_OFFB + BQ * KROWB * 2)     // +2304
#define KHI_OFFB   (QLO_OFFB + BQ * KROWB * 2)     // 136256 (16B aligned)
#define KLO_OFFB   (KHI_OFFB + KT * KROWB * 2)     // +36864
#define SMEM_BYTES (KLO_OFFB + KT * KROWB * 2)     // 209984
#define RED_OFFB   KHI_OFFB                        // reduce area overlays K/V tiles

// ---------------- helpers ----------------

__device__ __forceinline__ void mma16816(float c[4],
                                         uint32_t a0, uint32_t a1, uint32_t a2, uint32_t a3,
                                         uint32_t b0, uint32_t b1) {
    asm volatile(
        "mma.sync.aligned.m16n8k16.row.col.f32.bf16.bf16.f32 "
        "{%0,%1,%2,%3}, {%4,%5,%6,%7}, {%8,%9}, {%0,%1,%2,%3};"
        : "+f"(c[0]), "+f"(c[1]), "+f"(c[2]), "+f"(c[3])
        : "r"(a0), "r"(a1), "r"(a2), "r"(a3), "r"(b0), "r"(b1));
}

// pack two floats' bf16 roundings: low16 = bf16(a), high16 = bf16(b)
__device__ __forceinline__ uint32_t pack_bf2(float a, float b) {
    uint32_t r;
    asm("cvt.rn.bf16x2.f32 %0, %1, %2;" : "=r"(r) : "f"(b), "f"(a));
    return r;
}

// split pair (a,b) into packed hi and packed lo registers
__device__ __forceinline__ void split2(float a, float b, uint32_t& hi, uint32_t& lo) {
    __nv_bfloat16 ha = __float2bfloat16_rn(a);
    __nv_bfloat16 hb = __float2bfloat16_rn(b);
    __nv_bfloat162 hh = __halves2bfloat162(ha, hb);
    hi = *reinterpret_cast<uint32_t*>(&hh);
    float la = a - __bfloat162float(ha);
    float lb = b - __bfloat162float(hb);
    lo = pack_bf2(la, lb);
}

struct alignas(8) U2 { uint32_t x, y; };

// convert float4 -> 4 bf16 hi (uint2) and 4 bf16 lo (uint2)
__device__ __forceinline__ void cvt_hl4(float4 v, U2& hi, U2& lo) {
    split2(v.x, v.y, hi.x, lo.x);
    split2(v.z, v.w, hi.y, lo.y);
}

__global__ __launch_bounds__(NTHREADS, 1)
void attn_alibi_kernel(const float* __restrict__ Q, const float* __restrict__ K,
                       const float* __restrict__ V, const int* __restrict__ Msk,
                       const float* __restrict__ Alb, float* __restrict__ Out,
                       float* __restrict__ P) {
    extern __shared__ char smraw[];
    float*         s    = reinterpret_cast<float*>(smraw + S_OFFB);     // [BQ][SROW]
    float*         rinv = reinterpret_cast<float*>(smraw + RINV_OFFB);  // [BQ]
    __nv_bfloat16* q_hi = reinterpret_cast<__nv_bfloat16*>(smraw + QHI_OFFB);
    __nv_bfloat16* q_lo = reinterpret_cast<__nv_bfloat16*>(smraw + QLO_OFFB);
    __nv_bfloat16* k_hi = reinterpret_cast<__nv_bfloat16*>(smraw + KHI_OFFB);
    __nv_bfloat16* k_lo = reinterpret_cast<__nv_bfloat16*>(smraw + KLO_OFFB);
    float*         red  = reinterpret_cast<float*>(smraw + RED_OFFB);   // overlays K/V

    const int h  = blockIdx.x;
    const int qb = blockIdx.y;
    const int b  = blockIdx.z;
    const int t  = threadIdx.x;
    const int w  = t >> 5;
    const int l  = t & 31;
    const int lg = l >> 2;      // mma group id (0..7)
    const int lt = l & 3;       // thread-in-group

    const size_t bh = (size_t)b * H_ + h;
    const float* Qp = Q + (bh * S_ + (size_t)qb * BQ) * D_;
    const float* Kp = K + bh * S_ * D_;
    const float* Vp = V + bh * S_ * D_;

    // ---- stage Q as bf16 hi/lo: 256 float4s, one per thread ----
    {
        int row = t >> 4, d4 = t & 15;
        float4 v = reinterpret_cast<const float4*>(Qp)[row * 16 + d4];
        U2 hi, lo; cvt_hl4(v, hi, lo);
        *reinterpret_cast<U2*>(&q_hi[row * KROWB + d4 * 4]) = hi;
        *reinterpret_cast<U2*>(&q_lo[row * KROWB + d4 * 4]) = lo;
    }

    // ================= Phase 1: scores = Q K^T via bf16-split MMA =================
    for (int k0 = 0; k0 < S_; k0 += KT) {
        __syncthreads();   // q ready (iter 0) / previous tile consumed
        const float4* Ksrc = reinterpret_cast<const float4*>(Kp + (size_t)k0 * D_);
        #pragma unroll
        for (int it = 0; it < 16; ++it) {
            int idx = t + it * NTHREADS;           // 0..4095
            int row = idx >> 4, d4 = idx & 15;
            U2 hi, lo; cvt_hl4(Ksrc[idx], hi, lo);
            *reinterpret_cast<U2*>(&k_hi[row * KROWB + d4 * 4]) = hi;
            *reinterpret_cast<U2*>(&k_lo[row * KROWB + d4 * 4]) = lo;
        }
        __syncthreads();

        float acc[4][4];
        #pragma unroll
        for (int nt = 0; nt < 4; ++nt)
            #pragma unroll
            for (int j = 0; j < 4; ++j) acc[nt][j] = 0.0f;

        #pragma unroll
        for (int ks = 0; ks < 4; ++ks) {
            const int c0 = ks * 16 + lt * 2;
            uint32_t ah[4], al[4];
            ah[0] = *reinterpret_cast<uint32_t*>(&q_hi[lg * KROWB + c0]);
            ah[1] = *reinterpret_cast<uint32_t*>(&q_hi[(lg + 8) * KROWB + c0]);
            ah[2] = *reinterpret_cast<uint32_t*>(&q_hi[lg * KROWB + c0 + 8]);
            ah[3] = *reinterpret_cast<uint32_t*>(&q_hi[(lg + 8) * KROWB + c0 + 8]);
            al[0] = *reinterpret_cast<uint32_t*>(&q_lo[lg * KROWB + c0]);
            al[1] = *reinterpret_cast<uint32_t*>(&q_lo[(lg + 8) * KROWB + c0]);
            al[2] = *reinterpret_cast<uint32_t*>(&q_lo[lg * KROWB + c0 + 8]);
            al[3] = *reinterpret_cast<uint32_t*>(&q_lo[(lg + 8) * KROWB + c0 + 8]);

            #pragma unroll
            for (int nt = 0; nt < 4; ++nt) {
                const int base = (w * 32 + nt * 8 + lg) * KROWB + c0;
                uint32_t kb0 = *reinterpret_cast<uint32_t*>(&k_hi[base]);
                uint32_t kb1 = *reinterpret_cast<uint32_t*>(&k_hi[base + 8]);
                uint32_t kl0 = *reinterpret_cast<uint32_t*>(&k_lo[base]);
                uint32_t kl1 = *reinterpret_cast<uint32_t*>(&k_lo[base + 8]);
                mma16816(acc[nt], ah[0], ah[1], ah[2], ah[3], kb0, kb1);
                mma16816(acc[nt], ah[0], ah[1], ah[2], ah[3], kl0, kl1);
                mma16816(acc[nt], al[0], al[1], al[2], al[3], kb0, kb1);
            }
        }
        #pragma unroll
        for (int nt = 0; nt < 4; ++nt) {
            const int col = k0 + w * 32 + nt * 8 + lt * 2;
            *reinterpret_cast<float2*>(&s[lg * SROW + col])       = make_float2(acc[nt][0], acc[nt][1]);
            *reinterpret_cast<float2*>(&s[(lg + 8) * SROW + col]) = make_float2(acc[nt][2], acc[nt][3]);
        }
    }
    __syncthreads();

    // ========= Phase 2: scale + alibi + mask + exact softmax =========
    {
        const float slope = exp2f(-8.0f * (float)(h + 1) / (float)H_);
        const float* al = Alb + ((size_t)b * S_ + (size_t)qb * BQ) * S_;
        const int*   mk = Msk + ((size_t)b * S_ + (size_t)qb * BQ) * S_;

        #pragma unroll
        for (int rr = 0; rr < 2; ++rr) {
            const int r = w * 2 + rr;
            float*       srow = s  + (size_t)r * SROW;
            const float* arow = al + (size_t)r * S_;
            const int*   mrow = mk + (size_t)r * S_;

            float m = -3.0e38f;
            for (int k = l; k < S_; k += 32) {
                float v = srow[k] * 0.125f + arow[k] * slope;
                if (mrow[k] == 0) v = -1.0e9f;
                srow[k] = v;
                m = fmaxf(m, v);
            }
            #pragma unroll
            for (int off = 16; off > 0; off >>= 1)
                m = fmaxf(m, __shfl_xor_sync(0xffffffffu, m, off));

            float sum = 0.0f;
            for (int k = l; k < S_; k += 32) {
                float e = __expf(srow[k] - m);
                srow[k] = e;        // keep UNNORMALIZED
                sum += e;
            }
            #pragma unroll
            for (int off = 16; off > 0; off >>= 1)
                sum += __shfl_xor_sync(0xffffffffu, sum, off);
            const float inv = 1.0f / sum;
            if (l == 0) rinv[r] = inv;

            if (P) {
                float* prow = P + ((bh * S_ + (size_t)qb * BQ + r)) * S_;
                for (int k = l; k < S_; k += 32)
                    prow[k] = srow[k] * inv;
            }
        }
    }

    // ================= Phase 3: Out = P @ V via bf16-split MMA =================
    {
        float oacc[8][4];
        #pragma unroll
        for (int nt = 0; nt < 8; ++nt)
            #pragma unroll
            for (int j = 0; j < 4; ++j) oacc[nt][j] = 0.0f;

        const unsigned short* vh16 = reinterpret_cast<const unsigned short*>(k_hi);
        const unsigned short* vl16 = reinterpret_cast<const unsigned short*>(k_lo);

        for (int kb = 0; kb < S_; kb += KT) {
            __syncthreads();   // previous tile consumed (and strip ready, iter 0)
            const float4* Vsrc = reinterpret_cast<const float4*>(Vp + (size_t)kb * D_);
            #pragma unroll
            for (int it = 0; it < 16; ++it) {
                int idx = t + it * NTHREADS;
                int row = idx >> 4, d4 = idx & 15;
                U2 hi, lo; cvt_hl4(Vsrc[idx], hi, lo);
                *reinterpret_cast<U2*>(&k_hi[row * KROWB + d4 * 4]) = hi;
                *reinterpret_cast<U2*>(&k_lo[row * KROWB + d4 * 4]) = lo;
            }
            __syncthreads();

            #pragma unroll
            for (int ks = 0; ks < 2; ++ks) {
                const int ka = kb + w * 32 + ks * 16 + lt * 2;  // absolute strip col
                const int kl = w * 32 + ks * 16 + lt * 2;       // tile-local V row
                // A fragments from fp32 strip -> bf16 hi/lo
                float2 p00 = *reinterpret_cast<const float2*>(&s[lg * SROW + ka]);
                float2 p10 = *reinterpret_cast<const float2*>(&s[(lg + 8) * SROW + ka]);
                float2 p01 = *reinterpret_cast<const float2*>(&s[lg * SROW + ka + 8]);
                float2 p11 = *reinterpret_cast<const float2*>(&s[(lg + 8) * SROW + ka + 8]);
                uint32_t ah[4], al4[4];
                split2(p00.x, p00.y, ah[0], al4[0]);
                split2(p10.x, p10.y, ah[1], al4[1]);
                split2(p01.x, p01.y, ah[2], al4[2]);
                split2(p11.x, p11.y, ah[3], al4[3]);

                #pragma unroll
                for (int nt = 0; nt < 8; ++nt) {
                    const int n = nt * 8 + lg;
                    uint32_t vb0 = (uint32_t)vh16[kl * KROWB + n] |
                                   ((uint32_t)vh16[(kl + 1) * KROWB + n] << 16);
                    uint32_t vb1 = (uint32_t)vh16[(kl + 8) * KROWB + n] |
                                   ((uint32_t)vh16[(kl + 9) * KROWB + n] << 16);
                    uint32_t vc0 = (uint32_t)vl16[kl * KROWB + n] |
                                   ((uint32_t)vl16[(kl + 1) * KROWB + n] << 16);
                    uint32_t vc1 = (uint32_t)vl16[(kl + 8) * KROWB + n] |
                                   ((uint32_t)vl16[(kl + 9) * KROWB + n] << 16);
                    mma16816(oacc[nt], ah[0], ah[1], ah[2], ah[3], vb0, vb1);
                    mma16816(oacc[nt], ah[0], ah[1], ah[2], ah[3], vc0, vc1);
                    mma16816(oacc[nt], al4[0], al4[1], al4[2], al4[3], vb0, vb1);
                }
            }
        }

        // cross-warp k-reduction through smem (V buffers free now)
        __syncthreads();
        #pragma unroll
        for (int nt = 0; nt < 8; ++nt) {
            const int col = nt * 8 + lt * 2;
            *reinterpret_cast<float2*>(&red[w * (BQ * REDROW) + lg * REDROW + col]) =
                make_float2(oacc[nt][0], oacc[nt][1]);
            *reinterpret_cast<float2*>(&red[w * (BQ * REDROW) + (lg + 8) * REDROW + col]) =
                make_float2(oacc[nt][2], oacc[nt][3]);
        }
        __syncthreads();

        {
            const int row = t >> 4, n0 = (t & 15) * 4;
            float4 acc4 = make_float4(0.f, 0.f, 0.f, 0.f);
            #pragma unroll
            for (int ww = 0; ww < 8; ++ww) {
                float4 v = *reinterpret_cast<const float4*>(
                    &red[ww * (BQ * REDROW) + row * REDROW + n0]);
                acc4.x += v.x; acc4.y += v.y; acc4.z += v.z; acc4.w += v.w;
            }
            const float invs = rinv[row];
            acc4.x *= invs; acc4.y *= invs; acc4.z *= invs; acc4.w *= invs;
            float* orow = Out + (bh * S_ + (size_t)qb * BQ + row) * D_;
            *reinterpret_cast<float4*>(&orow[n0]) = acc4;
        }
    }
}

extern "C" void kernel_launch(void* const* d_in, const int* in_sizes, int n_in,
                              void* d_out, int out_size) {
    const float* Q  = (const float*)d_in[0];
    const float* K  = (const float*)d_in[1];
    const float* V  = (const float*)d_in[2];
    const int*   M  = (const int*)d_in[3];
    const float* A  = (const float*)d_in[4];
    float* Out = (float*)d_out;

    const long long OUT_E = (long long)B_ * H_ * S_ * D_;             // 4,194,304
    const long long P_E   = (long long)B_ * H_ * S_ * (long long)S_;  // 134,217,728
    float* P = ((long long)out_size >= OUT_E + P_E) ? (Out + OUT_E) : nullptr;

    cudaFuncSetAttribute(attn_alibi_kernel,
                         cudaFuncAttributeMaxDynamicSharedMemorySize, SMEM_BYTES);

    dim3 grid(H_, S_ / BQ, B_);   // h fastest -> mask/alibi L2 reuse across heads
    attn_alibi_kernel<<<grid, NTHREADS, SMEM_BYTES>>>(Q, K, V, M, A, Out, P);
}

// round 6
// speedup vs baseline: 1.5838x; 1.1647x over previous
#include <cuda_runtime.h>
#include <cuda_bf16.h>
#include <stdint.h>
#include <math.h>

// Problem constants
#define B_ 2
#define H_ 16
#define S_ 2048
#define D_ 64

// Tiling
#define BQ 16          // query rows per CTA
#define KT 256         // K/V rows staged per tile
#define NTHREADS 512   // 16 warps

#define KROWB 72       // bf16 elems per staged K row (64 + 8 pad)
#define SROW  2056     // fp32 score-strip row stride
#define REDROW 68      // fp32 reduce-area row stride
#define KWV   132      // uint32 words per transposed-V row (128 + 4 pad)

// Shared memory byte offsets
#define S_OFFB     0
#define RINV_OFFB  (BQ * SROW * 4)                 // 131584
#define QHI_OFFB   (RINV_OFFB + 64)                // 131648
#define QLO_OFFB   (QHI_OFFB + BQ * KROWB * 2)     // +2304
#define KHI_OFFB   (QLO_OFFB + BQ * KROWB * 2)     // 136256
#define KLO_OFFB   (KHI_OFFB + KT * KROWB * 2)     // +36864
#define SMEM_BYTES (KLO_OFFB + KT * KROWB * 2)     // 209984
#define RED_OFFB   KHI_OFFB                        // reduce area overlays K/V region
#define VTHI_OFFB  KHI_OFFB                        // transposed V hi: 64*132*4 = 33792 B
#define VTLO_OFFB  KLO_OFFB                        // transposed V lo

// ---------------- helpers ----------------

__device__ __forceinline__ void mma16816(float c[4],
                                         uint32_t a0, uint32_t a1, uint32_t a2, uint32_t a3,
                                         uint32_t b0, uint32_t b1) {
    asm volatile(
        "mma.sync.aligned.m16n8k16.row.col.f32.bf16.bf16.f32 "
        "{%0,%1,%2,%3}, {%4,%5,%6,%7}, {%8,%9}, {%0,%1,%2,%3};"
        : "+f"(c[0]), "+f"(c[1]), "+f"(c[2]), "+f"(c[3])
        : "r"(a0), "r"(a1), "r"(a2), "r"(a3), "r"(b0), "r"(b1));
}

__device__ __forceinline__ uint32_t pack_bf2(float a, float b) {
    uint32_t r;
    asm("cvt.rn.bf16x2.f32 %0, %1, %2;" : "=r"(r) : "f"(b), "f"(a));
    return r;
}

// split pair (a,b): hi = {bf16(a) lo16, bf16(b) hi16}; lo = residuals likewise
__device__ __forceinline__ void split2(float a, float b, uint32_t& hi, uint32_t& lo) {
    __nv_bfloat16 ha = __float2bfloat16_rn(a);
    __nv_bfloat16 hb = __float2bfloat16_rn(b);
    __nv_bfloat162 hh = __halves2bfloat162(ha, hb);
    hi = *reinterpret_cast<uint32_t*>(&hh);
    float la = a - __bfloat162float(ha);
    float lb = b - __bfloat162float(hb);
    lo = pack_bf2(la, lb);
}

struct alignas(8) U2 { uint32_t x, y; };

__device__ __forceinline__ void cvt_hl4(float4 v, U2& hi, U2& lo) {
    split2(v.x, v.y, hi.x, lo.x);
    split2(v.z, v.w, hi.y, lo.y);
}

// swizzle term for transposed-V layout
__device__ __forceinline__ int vswz(int d) { return (d ^ (d >> 3)) & 3; }

__global__ __launch_bounds__(NTHREADS, 1)
void attn_alibi_kernel(const float* __restrict__ Q, const float* __restrict__ K,
                       const float* __restrict__ V, const int* __restrict__ Msk,
                       const float* __restrict__ Alb, float* __restrict__ Out,
                       float* __restrict__ P) {
    extern __shared__ char smraw[];
    float*         s    = reinterpret_cast<float*>(smraw + S_OFFB);     // [BQ][SROW]
    float*         rinv = reinterpret_cast<float*>(smraw + RINV_OFFB);  // [BQ]
    __nv_bfloat16* q_hi = reinterpret_cast<__nv_bfloat16*>(smraw + QHI_OFFB);
    __nv_bfloat16* q_lo = reinterpret_cast<__nv_bfloat16*>(smraw + QLO_OFFB);
    __nv_bfloat16* k_hi = reinterpret_cast<__nv_bfloat16*>(smraw + KHI_OFFB);
    __nv_bfloat16* k_lo = reinterpret_cast<__nv_bfloat16*>(smraw + KLO_OFFB);
    uint32_t*      vthi = reinterpret_cast<uint32_t*>(smraw + VTHI_OFFB); // [64][KWV]
    uint32_t*      vtlo = reinterpret_cast<uint32_t*>(smraw + VTLO_OFFB);
    float*         red  = reinterpret_cast<float*>(smraw + RED_OFFB);   // [8][BQ][REDROW]

    const int h  = blockIdx.x;
    const int qb = blockIdx.y;
    const int b  = blockIdx.z;
    const int t  = threadIdx.x;
    const int w  = t >> 5;      // warp 0..15
    const int l  = t & 31;
    const int lg = l >> 2;      // mma group id (0..7)
    const int lt = l & 3;       // thread-in-group

    const size_t bh = (size_t)b * H_ + h;
    const float* Qp = Q + (bh * S_ + (size_t)qb * BQ) * D_;
    const float* Kp = K + bh * S_ * D_;
    const float* Vp = V + bh * S_ * D_;

    // ---- stage Q as bf16 hi/lo: 256 float4s ----
    if (t < 256) {
        int row = t >> 4, d4 = t & 15;
        float4 v = reinterpret_cast<const float4*>(Qp)[row * 16 + d4];
        U2 hi, lo; cvt_hl4(v, hi, lo);
        *reinterpret_cast<U2*>(&q_hi[row * KROWB + d4 * 4]) = hi;
        *reinterpret_cast<U2*>(&q_lo[row * KROWB + d4 * 4]) = lo;
    }

    // ================= Phase 1: scores = Q K^T via bf16-split MMA =================
    for (int k0 = 0; k0 < S_; k0 += KT) {
        __syncthreads();
        const float4* Ksrc = reinterpret_cast<const float4*>(Kp + (size_t)k0 * D_);
        #pragma unroll
        for (int it = 0; it < 8; ++it) {
            int idx = t + it * NTHREADS;           // 0..4095
            int row = idx >> 4, d4 = idx & 15;
            U2 hi, lo; cvt_hl4(Ksrc[idx], hi, lo);
            *reinterpret_cast<U2*>(&k_hi[row * KROWB + d4 * 4]) = hi;
            *reinterpret_cast<U2*>(&k_lo[row * KROWB + d4 * 4]) = lo;
        }
        __syncthreads();

        float acc[2][4];
        #pragma unroll
        for (int nt = 0; nt < 2; ++nt)
            #pragma unroll
            for (int j = 0; j < 4; ++j) acc[nt][j] = 0.0f;

        #pragma unroll
        for (int ks = 0; ks < 4; ++ks) {
            const int c0 = ks * 16 + lt * 2;
            uint32_t ah[4], al[4];
            ah[0] = *reinterpret_cast<uint32_t*>(&q_hi[lg * KROWB + c0]);
            ah[1] = *reinterpret_cast<uint32_t*>(&q_hi[(lg + 8) * KROWB + c0]);
            ah[2] = *reinterpret_cast<uint32_t*>(&q_hi[lg * KROWB + c0 + 8]);
            ah[3] = *reinterpret_cast<uint32_t*>(&q_hi[(lg + 8) * KROWB + c0 + 8]);
            al[0] = *reinterpret_cast<uint32_t*>(&q_lo[lg * KROWB + c0]);
            al[1] = *reinterpret_cast<uint32_t*>(&q_lo[(lg + 8) * KROWB + c0]);
            al[2] = *reinterpret_cast<uint32_t*>(&q_lo[lg * KROWB + c0 + 8]);
            al[3] = *reinterpret_cast<uint32_t*>(&q_lo[(lg + 8) * KROWB + c0 + 8]);

            #pragma unroll
            for (int nt = 0; nt < 2; ++nt) {
                const int base = (w * 16 + nt * 8 + lg) * KROWB + c0;
                uint32_t kb0 = *reinterpret_cast<uint32_t*>(&k_hi[base]);
                uint32_t kb1 = *reinterpret_cast<uint32_t*>(&k_hi[base + 8]);
                uint32_t kl0 = *reinterpret_cast<uint32_t*>(&k_lo[base]);
                uint32_t kl1 = *reinterpret_cast<uint32_t*>(&k_lo[base + 8]);
                mma16816(acc[nt], ah[0], ah[1], ah[2], ah[3], kb0, kb1);
                mma16816(acc[nt], ah[0], ah[1], ah[2], ah[3], kl0, kl1);
                mma16816(acc[nt], al[0], al[1], al[2], al[3], kb0, kb1);
            }
        }
        #pragma unroll
        for (int nt = 0; nt < 2; ++nt) {
            const int col = k0 + w * 16 + nt * 8 + lt * 2;
            *reinterpret_cast<float2*>(&s[lg * SROW + col])       = make_float2(acc[nt][0], acc[nt][1]);
            *reinterpret_cast<float2*>(&s[(lg + 8) * SROW + col]) = make_float2(acc[nt][2], acc[nt][3]);
        }
    }
    __syncthreads();

    // ========= Phase 2: scale + alibi + mask + exact softmax (1 row per warp) =========
    {
        const float slope = exp2f(-8.0f * (float)(h + 1) / (float)H_);
        const float* al = Alb + ((size_t)b * S_ + (size_t)qb * BQ) * S_;
        const int*   mk = Msk + ((size_t)b * S_ + (size_t)qb * BQ) * S_;

        const int r = w;
        float*       srow = s  + (size_t)r * SROW;
        const float* arow = al + (size_t)r * S_;
        const int*   mrow = mk + (size_t)r * S_;

        float m = -3.0e38f;
        for (int k = l; k < S_; k += 32) {
            float v = srow[k] * 0.125f + arow[k] * slope;
            if (mrow[k] == 0) v = -1.0e9f;
            srow[k] = v;
            m = fmaxf(m, v);
        }
        #pragma unroll
        for (int off = 16; off > 0; off >>= 1)
            m = fmaxf(m, __shfl_xor_sync(0xffffffffu, m, off));

        float sum = 0.0f;
        for (int k = l; k < S_; k += 32) {
            float e = __expf(srow[k] - m);
            srow[k] = e;        // keep UNNORMALIZED
            sum += e;
        }
        #pragma unroll
        for (int off = 16; off > 0; off >>= 1)
            sum += __shfl_xor_sync(0xffffffffu, sum, off);
        const float inv = 1.0f / sum;
        if (l == 0) rinv[r] = inv;

        if (P) {
            float* prow = P + ((bh * S_ + (size_t)qb * BQ + r)) * S_;
            for (int k = l; k < S_; k += 32)
                prow[k] = srow[k] * inv;
        }
    }

    // ================= Phase 3: Out = P @ V via bf16-split MMA (transposed V) =======
    {
        const int g    = w >> 1;        // k-split group 0..7 (32 k per tile)
        const int half = w & 1;         // n half: cols half*32..+31

        float oacc[4][4];
        #pragma unroll
        for (int nt = 0; nt < 4; ++nt)
            #pragma unroll
            for (int j = 0; j < 4; ++j) oacc[nt][j] = 0.0f;

        const int dstage  = t & 63;     // this thread's d for V staging
        const int kp0     = t >> 6;     // 0..7
        const int swd     = vswz(dstage);

        for (int kb = 0; kb < S_; kb += KT) {
            __syncthreads();   // strip ready (iter 0) / previous tile consumed
            const float* Vt = Vp + (size_t)kb * D_;
            #pragma unroll
            for (int it = 0; it < 16; ++it) {
                const int kp = kp0 + it * 8;          // 0..127
                float v0 = Vt[(2 * kp) * D_ + dstage];
                float v1 = Vt[(2 * kp + 1) * D_ + dstage];
                uint32_t hw, lw; split2(v0, v1, hw, lw);
                const int col = kp ^ swd;
                vthi[dstage * KWV + col] = hw;
                vtlo[dstage * KWV + col] = lw;
            }
            __syncthreads();

            #pragma unroll
            for (int ks = 0; ks < 2; ++ks) {
                const int kl = g * 32 + ks * 16;        // tile-local k base
                const int ka = kb + kl + lt * 2;        // absolute strip col
                float2 p00 = *reinterpret_cast<const float2*>(&s[lg * SROW + ka]);
                float2 p10 = *reinterpret_cast<const float2*>(&s[(lg + 8) * SROW + ka]);
                float2 p01 = *reinterpret_cast<const float2*>(&s[lg * SROW + ka + 8]);
                float2 p11 = *reinterpret_cast<const float2*>(&s[(lg + 8) * SROW + ka + 8]);
                uint32_t ah[4], al4[4];
                split2(p00.x, p00.y, ah[0], al4[0]);
                split2(p10.x, p10.y, ah[1], al4[1]);
                split2(p01.x, p01.y, ah[2], al4[2]);
                split2(p11.x, p11.y, ah[3], al4[3]);

                const int kpb = (kl >> 1) + lt;         // low 2 bits = lt
                #pragma unroll
                for (int nt = 0; nt < 4; ++nt) {
                    const int n   = half * 32 + nt * 8 + lg;
                    const int swn = vswz(n);
                    uint32_t vb0 = vthi[n * KWV + (kpb ^ swn)];
                    uint32_t vb1 = vthi[n * KWV + ((kpb + 4) ^ swn)];
                    uint32_t vc0 = vtlo[n * KWV + (kpb ^ swn)];
                    uint32_t vc1 = vtlo[n * KWV + ((kpb + 4) ^ swn)];
                    mma16816(oacc[nt], ah[0], ah[1], ah[2], ah[3], vb0, vb1);
                    mma16816(oacc[nt], ah[0], ah[1], ah[2], ah[3], vc0, vc1);
                    mma16816(oacc[nt], al4[0], al4[1], al4[2], al4[3], vb0, vb1);
                }
            }
        }

        // cross-group k-reduction through smem (VT area free now)
        __syncthreads();
        #pragma unroll
        for (int nt = 0; nt < 4; ++nt) {
            const int col = half * 32 + nt * 8 + lt * 2;
            *reinterpret_cast<float2*>(&red[g * (BQ * REDROW) + lg * REDROW + col]) =
                make_float2(oacc[nt][0], oacc[nt][1]);
            *reinterpret_cast<float2*>(&red[g * (BQ * REDROW) + (lg + 8) * REDROW + col]) =
                make_float2(oacc[nt][2], oacc[nt][3]);
        }
        __syncthreads();

        if (t < 256) {
            const int row = t >> 4, n0 = (t & 15) * 4;
            float4 acc4 = make_float4(0.f, 0.f, 0.f, 0.f);
            #pragma unroll
            for (int gg = 0; gg < 8; ++gg) {
                float4 v = *reinterpret_cast<const float4*>(
                    &red[gg * (BQ * REDROW) + row * REDROW + n0]);
                acc4.x += v.x; acc4.y += v.y; acc4.z += v.z; acc4.w += v.w;
            }
            const float invs = rinv[row];
            acc4.x *= invs; acc4.y *= invs; acc4.z *= invs; acc4.w *= invs;
            float* orow = Out + (bh * S_ + (size_t)qb * BQ + row) * D_;
            *reinterpret_cast<float4*>(&orow[n0]) = acc4;
        }
    }
}

extern "C" void kernel_launch(void* const* d_in, const int* in_sizes, int n_in,
                              void* d_out, int out_size) {
    const float* Q  = (const float*)d_in[0];
    const float* K  = (const float*)d_in[1];
    const float* V  = (const float*)d_in[2];
    const int*   M  = (const int*)d_in[3];
    const float* A  = (const float*)d_in[4];
    float* Out = (float*)d_out;

    const long long OUT_E = (long long)B_ * H_ * S_ * D_;             // 4,194,304
    const long long P_E   = (long long)B_ * H_ * S_ * (long long)S_;  // 134,217,728
    float* P = ((long long)out_size >= OUT_E + P_E) ? (Out + OUT_E) : nullptr;

    cudaFuncSetAttribute(attn_alibi_kernel,
                         cudaFuncAttributeMaxDynamicSharedMemorySize, SMEM_BYTES);

    dim3 grid(H_, S_ / BQ, B_);   // h fastest -> mask/alibi L2 reuse across heads
    attn_alibi_kernel<<<grid, NTHREADS, SMEM_BYTES>>>(Q, K, V, M, A, Out, P);
}